// round 1
// baseline (speedup 1.0000x reference)
#include <cuda_runtime.h>
#include <cuda_bf16.h>

// Problem constants
#define BB   4
#define TT   2048
#define HID  2048
#define NH   16
#define HD   128
#define MTOT (BB * TT)          // 8192
#define KDIM 2048

// Scratch (device globals; allocation-free rule)
__device__ float g_Q[(size_t)BB * NH * TT * HD];
__device__ float g_K[(size_t)BB * NH * TT * HD];
__device__ float g_V[(size_t)BB * NH * TT * HD];
__device__ float g_attn[(size_t)BB * TT * HID];

// ---------------------------------------------------------------------------
// GEMM: C[M,N] = A[M,K] * Bw[N,K]^T   (both row-major, K contiguous)
// MODE 0: A = x, Bw = w_qkv (N=6144). Epilogue: RoPE on Q/K sections,
//         scale Q by 1/sqrt(HD), scatter to g_Q/g_K/g_V in [B,NH,T,HD].
// MODE 1: A = g_attn, Bw = w_proj (N=2048). Epilogue: + bias -> Cout.
// Tiling: 128x128x32, 256 threads, 8x8 per thread, reg prefetch.
// ---------------------------------------------------------------------------
template <int MODE>
__global__ __launch_bounds__(256, 2)
void gemm_kernel(const float* __restrict__ A,
                 const float* __restrict__ Bw,
                 const float* __restrict__ cosT,
                 const float* __restrict__ sinT,
                 const float* __restrict__ bias,
                 float* __restrict__ Cout)
{
    __shared__ float As[32][128];
    __shared__ float Bs[32][128];

    const int tid  = threadIdx.x;
    const int tx   = tid & 15;
    const int ty   = tid >> 4;
    const int row0 = blockIdx.x * 128;
    const int col0 = blockIdx.y * 128;

    const float* __restrict__ Ap = (MODE == 0) ? A : g_attn;

    // load mapping: 4 float4 per thread per operand
    int lr[4], lk[4];
#pragma unroll
    for (int i = 0; i < 4; i++) {
        int f = tid + i * 256;
        lr[i] = f >> 3;          // row within tile (0..127)
        lk[i] = (f & 7) * 4;     // k within tile (0..28 step 4)
    }

    float4 pa[4], pb[4];
#pragma unroll
    for (int i = 0; i < 4; i++) {
        pa[i] = *(const float4*)&Ap[(long)(row0 + lr[i]) * KDIM + lk[i]];
        pb[i] = *(const float4*)&Bw[(long)(col0 + lr[i]) * KDIM + lk[i]];
    }

    float acc[8][8];
#pragma unroll
    for (int i = 0; i < 8; i++)
#pragma unroll
        for (int j = 0; j < 8; j++) acc[i][j] = 0.0f;

    for (int kb = 0; kb < KDIM; kb += 32) {
        if (kb) __syncthreads();
#pragma unroll
        for (int i = 0; i < 4; i++) {
            As[lk[i] + 0][lr[i]] = pa[i].x;
            As[lk[i] + 1][lr[i]] = pa[i].y;
            As[lk[i] + 2][lr[i]] = pa[i].z;
            As[lk[i] + 3][lr[i]] = pa[i].w;
            Bs[lk[i] + 0][lr[i]] = pb[i].x;
            Bs[lk[i] + 1][lr[i]] = pb[i].y;
            Bs[lk[i] + 2][lr[i]] = pb[i].z;
            Bs[lk[i] + 3][lr[i]] = pb[i].w;
        }
        __syncthreads();

        if (kb + 32 < KDIM) {
#pragma unroll
            for (int i = 0; i < 4; i++) {
                pa[i] = *(const float4*)&Ap[(long)(row0 + lr[i]) * KDIM + kb + 32 + lk[i]];
                pb[i] = *(const float4*)&Bw[(long)(col0 + lr[i]) * KDIM + kb + 32 + lk[i]];
            }
        }

#pragma unroll
        for (int kk = 0; kk < 32; kk++) {
            float4 a0 = *(const float4*)&As[kk][ty * 8];
            float4 a1 = *(const float4*)&As[kk][ty * 8 + 4];
            float4 b0 = *(const float4*)&Bs[kk][tx * 8];
            float4 b1 = *(const float4*)&Bs[kk][tx * 8 + 4];
            float av[8] = {a0.x, a0.y, a0.z, a0.w, a1.x, a1.y, a1.z, a1.w};
            float bv[8] = {b0.x, b0.y, b0.z, b0.w, b1.x, b1.y, b1.z, b1.w};
#pragma unroll
            for (int i = 0; i < 8; i++)
#pragma unroll
                for (int j = 0; j < 8; j++)
                    acc[i][j] += av[i] * bv[j];
        }
    }

    if (MODE == 0) {
        const int sec  = col0 >> 11;           // 0=Q 1=K 2=V
        const int head = (col0 >> 7) & 15;
        const int d0   = tx * 8;
        float* dstBase = (sec == 0) ? g_Q : (sec == 1) ? g_K : g_V;
        const float qscale = 0.08838834764831845f;  // 1/sqrt(128)
#pragma unroll
        for (int i = 0; i < 8; i++) {
            int m = row0 + ty * 8 + i;
            int b = m >> 11;
            int t = m & 2047;
            float v[8];
#pragma unroll
            for (int j = 0; j < 8; j++) v[j] = acc[i][j];
            if (sec < 2) {
#pragma unroll
                for (int p = 0; p < 4; p++) {
                    float c = cosT[t * 64 + (d0 >> 1) + p];
                    float s = sinT[t * 64 + (d0 >> 1) + p];
                    float e = v[2 * p], o = v[2 * p + 1];
                    v[2 * p]     = e * c - o * s;
                    v[2 * p + 1] = e * s + o * c;
                }
                if (sec == 0) {
#pragma unroll
                    for (int j = 0; j < 8; j++) v[j] *= qscale;
                }
            }
            long idx = (((long)(b * NH + head) * TT + t) * HD) + d0;
            *(float4*)&dstBase[idx]     = make_float4(v[0], v[1], v[2], v[3]);
            *(float4*)&dstBase[idx + 4] = make_float4(v[4], v[5], v[6], v[7]);
        }
    } else {
        const int o0 = col0 + tx * 8;
        float bv[8];
#pragma unroll
        for (int j = 0; j < 8; j++) bv[j] = bias[o0 + j];
#pragma unroll
        for (int i = 0; i < 8; i++) {
            int m = row0 + ty * 8 + i;
            long idx = (long)m * HID + o0;
            *(float4*)&Cout[idx] = make_float4(acc[i][0] + bv[0], acc[i][1] + bv[1],
                                               acc[i][2] + bv[2], acc[i][3] + bv[3]);
            *(float4*)&Cout[idx + 4] = make_float4(acc[i][4] + bv[4], acc[i][5] + bv[5],
                                                   acc[i][6] + bv[6], acc[i][7] + bv[7]);
        }
    }
}

// ---------------------------------------------------------------------------
// Flash attention: one block per (b, h, q-tile of 64). KV tiles of 64.
// smem: Q/K xor-swizzled float4 tiles, V plain, P padded.
// Thread (ty,tx) 16x16: S frag 4(q)x4(k), O acc 4(q)x8(d split lo/hi 64).
// ---------------------------------------------------------------------------
#define ATTN_SMEM (3 * 64 * 32 * 16 + 64 * 68 * 4)   // 115712 bytes

__global__ __launch_bounds__(256)
void attn_kernel()
{
    extern __shared__ float4 sm4[];
    float4* Qs = sm4;
    float4* Ks = sm4 + 64 * 32;
    float4* Vs = sm4 + 2 * 64 * 32;
    float*  Ps = (float*)(sm4 + 3 * 64 * 32);   // [64][68]

    const int tid = threadIdx.x;
    const int tx  = tid & 15;
    const int ty  = tid >> 4;
    const int bh  = blockIdx.y;
    const int q0  = blockIdx.x * 64;

    const float* __restrict__ Qg = g_Q + (long)bh * TT * HD;
    const float* __restrict__ Kg = g_K + (long)bh * TT * HD;
    const float* __restrict__ Vg = g_V + (long)bh * TT * HD;

    // Q tile load (swizzled: c4 ^ ((r>>2)&7))
#pragma unroll
    for (int i = 0; i < 8; i++) {
        int f = tid + i * 256;
        int r = f >> 5, c4 = f & 31;
        Qs[r * 32 + (c4 ^ ((r >> 2) & 7))] =
            *(const float4*)&Qg[(long)(q0 + r) * HD + c4 * 4];
    }

    float m_run[4], l_run[4], o_acc[4][8];
#pragma unroll
    for (int qi = 0; qi < 4; qi++) {
        m_run[qi] = -3.0e38f;
        l_run[qi] = 0.0f;
#pragma unroll
        for (int j = 0; j < 8; j++) o_acc[qi][j] = 0.0f;
    }

    const int qsw = ty & 7;
    const int ksw = tx & 7;

    for (int kv = 0; kv < TT; kv += 64) {
        __syncthreads();   // prev PV done (and 1st-iter Q ordering via next barrier)
#pragma unroll
        for (int i = 0; i < 8; i++) {
            int f = tid + i * 256;
            int r = f >> 5, c4 = f & 31;
            Ks[r * 32 + (c4 ^ ((r >> 2) & 7))] =
                *(const float4*)&Kg[(long)(kv + r) * HD + c4 * 4];
            Vs[r * 32 + c4] =
                *(const float4*)&Vg[(long)(kv + r) * HD + c4 * 4];
        }
        __syncthreads();

        // S = Q . K^T  (q pre-scaled by 1/sqrt(HD))
        float s[4][4];
#pragma unroll
        for (int qi = 0; qi < 4; qi++)
#pragma unroll
            for (int ki = 0; ki < 4; ki++) s[qi][ki] = 0.0f;

#pragma unroll 4
        for (int d4 = 0; d4 < 32; d4++) {
            float4 qf[4], kf[4];
#pragma unroll
            for (int qi = 0; qi < 4; qi++)
                qf[qi] = Qs[(ty * 4 + qi) * 32 + (d4 ^ qsw)];
#pragma unroll
            for (int ki = 0; ki < 4; ki++)
                kf[ki] = Ks[(tx * 4 + ki) * 32 + (d4 ^ ksw)];
#pragma unroll
            for (int qi = 0; qi < 4; qi++)
#pragma unroll
                for (int ki = 0; ki < 4; ki++) {
                    s[qi][ki] += qf[qi].x * kf[ki].x;
                    s[qi][ki] += qf[qi].y * kf[ki].y;
                    s[qi][ki] += qf[qi].z * kf[ki].z;
                    s[qi][ki] += qf[qi].w * kf[ki].w;
                }
        }

        // online softmax (row reductions over the 16 tx lanes)
#pragma unroll
        for (int qi = 0; qi < 4; qi++) {
            float mx = fmaxf(fmaxf(s[qi][0], s[qi][1]), fmaxf(s[qi][2], s[qi][3]));
#pragma unroll
            for (int off = 8; off >= 1; off >>= 1)
                mx = fmaxf(mx, __shfl_xor_sync(0xffffffffu, mx, off));
            float mn    = fmaxf(m_run[qi], mx);
            float alpha = __expf(m_run[qi] - mn);
            float sum   = 0.0f;
#pragma unroll
            for (int ki = 0; ki < 4; ki++) {
                float p = __expf(s[qi][ki] - mn);
                s[qi][ki] = p;
                sum += p;
            }
#pragma unroll
            for (int off = 8; off >= 1; off >>= 1)
                sum += __shfl_xor_sync(0xffffffffu, sum, off);
            l_run[qi] = l_run[qi] * alpha + sum;
            m_run[qi] = mn;
#pragma unroll
            for (int j = 0; j < 8; j++) o_acc[qi][j] *= alpha;
#pragma unroll
            for (int ki = 0; ki < 4; ki++)
                Ps[(ty * 4 + qi) * 68 + tx * 4 + ki] = s[qi][ki];
        }
        __syncthreads();

        // O += P . V   (d split: cols [tx*4, tx*4+3] and [64+tx*4 ...])
#pragma unroll 4
        for (int k = 0; k < 64; k++) {
            float4 v0 = Vs[k * 32 + tx];
            float4 v1 = Vs[k * 32 + 16 + tx];
#pragma unroll
            for (int qi = 0; qi < 4; qi++) {
                float p = Ps[(ty * 4 + qi) * 68 + k];
                o_acc[qi][0] += p * v0.x;
                o_acc[qi][1] += p * v0.y;
                o_acc[qi][2] += p * v0.z;
                o_acc[qi][3] += p * v0.w;
                o_acc[qi][4] += p * v1.x;
                o_acc[qi][5] += p * v1.y;
                o_acc[qi][6] += p * v1.z;
                o_acc[qi][7] += p * v1.w;
            }
        }
    }

    // finalize: /l, write [B,T,NH*HD]
    const int b = bh >> 4, h = bh & 15;
#pragma unroll
    for (int qi = 0; qi < 4; qi++) {
        float inv = 1.0f / l_run[qi];
        int t = q0 + ty * 4 + qi;
        long base = ((long)(b * TT + t)) * HID + h * HD;
        *(float4*)&g_attn[base + tx * 4] =
            make_float4(o_acc[qi][0] * inv, o_acc[qi][1] * inv,
                        o_acc[qi][2] * inv, o_acc[qi][3] * inv);
        *(float4*)&g_attn[base + 64 + tx * 4] =
            make_float4(o_acc[qi][4] * inv, o_acc[qi][5] * inv,
                        o_acc[qi][6] * inv, o_acc[qi][7] * inv);
    }
}

// ---------------------------------------------------------------------------
extern "C" void kernel_launch(void* const* d_in, const int* in_sizes, int n_in,
                              void* d_out, int out_size)
{
    const float* x      = (const float*)d_in[0];
    const float* w_qkv  = (const float*)d_in[1];
    const float* w_proj = (const float*)d_in[2];
    const float* b_proj = (const float*)d_in[3];
    const float* cosT   = (const float*)d_in[4];
    const float* sinT   = (const float*)d_in[5];
    float* out = (float*)d_out;

    cudaFuncSetAttribute(attn_kernel,
                         cudaFuncAttributeMaxDynamicSharedMemorySize, ATTN_SMEM);

    // 1) QKV proj + RoPE + scatter
    gemm_kernel<0><<<dim3(MTOT / 128, (3 * HID) / 128), 256>>>(
        x, w_qkv, cosT, sinT, nullptr, nullptr);

    // 2) attention
    attn_kernel<<<dim3(TT / 64, BB * NH), 256, ATTN_SMEM>>>();

    // 3) out proj + bias
    gemm_kernel<1><<<dim3(MTOT / 128, HID / 128), 256>>>(
        nullptr, w_proj, nullptr, nullptr, b_proj, out);
}

// round 2
// speedup vs baseline: 3.1607x; 3.1607x over previous
#include <cuda_runtime.h>
#include <cstdint>

// Problem constants
#define BB   4
#define TT   2048
#define HID  2048
#define NH   16
#define HD   128
#define MTOT (BB * TT)          // 8192
#define KDIM 2048

// Scratch (device globals; allocation-free rule)
__device__ float g_Q [(size_t)BB * NH * TT * HD];
__device__ float g_K [(size_t)BB * NH * TT * HD];
__device__ float g_Vt[(size_t)BB * NH * HD * TT];   // V pre-transposed: [bh][d][t]
__device__ float g_attn[(size_t)MTOT * HID];

// ---------------------------------------------------------------------------
// tf32 helpers
// ---------------------------------------------------------------------------
__device__ __forceinline__ uint32_t f2tf(float x) {
    uint32_t r;
    asm("cvt.rna.tf32.f32 %0, %1;" : "=r"(r) : "f"(x));
    return r;
}
__device__ __forceinline__ float f2tff(float x) { return __uint_as_float(f2tf(x)); }

__device__ __forceinline__ void mma8(float* c, const uint32_t* a, const uint32_t* b) {
    asm volatile(
        "mma.sync.aligned.m16n8k8.row.col.f32.tf32.tf32.f32 "
        "{%0,%1,%2,%3},{%4,%5,%6,%7},{%8,%9},{%0,%1,%2,%3};\n"
        : "+f"(c[0]), "+f"(c[1]), "+f"(c[2]), "+f"(c[3])
        : "r"(a[0]), "r"(a[1]), "r"(a[2]), "r"(a[3]), "r"(b[0]), "r"(b[1]));
}

// ---------------------------------------------------------------------------
// GEMM: C[M,N] = A[M,K] * Bw[N,K]^T  via m16n8k8 tf32 mma.
// Tiles 128x128x32, 256 threads = 8 warps (2m x 4n), warp tile 64x32.
// smem A/B: row-major [128][36] (pad 36 -> conflict-free fragment LDS).
// MODE 0: A=x, Bw=w_qkv; epilogue RoPE + qscale, scatter Q/K (and V transposed).
// MODE 1: A=g_attn, Bw=w_proj; epilogue + bias -> Cout.
// ---------------------------------------------------------------------------
#define LDS_AB 36

template <int MODE>
__global__ __launch_bounds__(256, 1)
void gemm_kernel(const float* __restrict__ A,
                 const float* __restrict__ Bw,
                 const float* __restrict__ cosT,
                 const float* __restrict__ sinT,
                 const float* __restrict__ bias,
                 float* __restrict__ Cout)
{
    __shared__ float As[128 * LDS_AB];
    __shared__ float Bs[128 * LDS_AB];

    const int tid  = threadIdx.x;
    const int lane = tid & 31;
    const int w    = tid >> 5;
    const int gy   = lane >> 2;   // 0..7
    const int gx   = lane & 3;    // 0..3
    const int wm   = (w >> 2) * 64;
    const int wn   = (w & 3) * 32;
    const long row0 = (long)blockIdx.x * 128;
    const long col0 = (long)blockIdx.y * 128;

    const float* __restrict__ Ap = (MODE == 0) ? A : g_attn;

    // load mapping: 4 float4 per thread per operand
    int lr[4], lk[4];
#pragma unroll
    for (int i = 0; i < 4; i++) {
        int f = tid + i * 256;
        lr[i] = f >> 3;          // 0..127
        lk[i] = (f & 7) * 4;     // 0..28
    }

    float4 pa[4], pb[4];
#pragma unroll
    for (int i = 0; i < 4; i++) {
        pa[i] = *(const float4*)&Ap[(row0 + lr[i]) * KDIM + lk[i]];
        pb[i] = *(const float4*)&Bw[(col0 + lr[i]) * KDIM + lk[i]];
    }

    float acc[4][4][4];
#pragma unroll
    for (int s = 0; s < 4; s++)
#pragma unroll
        for (int t = 0; t < 4; t++)
#pragma unroll
            for (int j = 0; j < 4; j++) acc[s][t][j] = 0.0f;

    for (int kb = 0; kb < KDIM; kb += 32) {
        if (kb) __syncthreads();
#pragma unroll
        for (int i = 0; i < 4; i++) {
            float* da = &As[lr[i] * LDS_AB + lk[i]];
            da[0] = f2tff(pa[i].x); da[1] = f2tff(pa[i].y);
            da[2] = f2tff(pa[i].z); da[3] = f2tff(pa[i].w);
            float* db = &Bs[lr[i] * LDS_AB + lk[i]];
            db[0] = f2tff(pb[i].x); db[1] = f2tff(pb[i].y);
            db[2] = f2tff(pb[i].z); db[3] = f2tff(pb[i].w);
        }
        __syncthreads();

        if (kb + 32 < KDIM) {
#pragma unroll
            for (int i = 0; i < 4; i++) {
                pa[i] = *(const float4*)&Ap[(row0 + lr[i]) * KDIM + kb + 32 + lk[i]];
                pb[i] = *(const float4*)&Bw[(col0 + lr[i]) * KDIM + kb + 32 + lk[i]];
            }
        }

#pragma unroll
        for (int ks = 0; ks < 4; ks++) {
            const int k0 = ks * 8;
            uint32_t af[4][4], bf[4][2];
#pragma unroll
            for (int s = 0; s < 4; s++) {
                const float* p = &As[(wm + 16 * s + gy) * LDS_AB + k0 + gx];
                af[s][0] = __float_as_uint(p[0]);
                af[s][1] = __float_as_uint(p[8 * LDS_AB]);
                af[s][2] = __float_as_uint(p[4]);
                af[s][3] = __float_as_uint(p[8 * LDS_AB + 4]);
            }
#pragma unroll
            for (int t = 0; t < 4; t++) {
                const float* p = &Bs[(wn + 8 * t + gy) * LDS_AB + k0 + gx];
                bf[t][0] = __float_as_uint(p[0]);
                bf[t][1] = __float_as_uint(p[4]);
            }
#pragma unroll
            for (int s = 0; s < 4; s++)
#pragma unroll
                for (int t = 0; t < 4; t++)
                    mma8(acc[s][t], af[s], bf[t]);
        }
    }

    // Epilogue. C mapping: rows wm+16s+gy(+8), cols wn+8t+2gx(+1).
    if (MODE == 0) {
        const int sec  = (int)(col0 >> 11);          // 0=Q 1=K 2=V
        const int head = ((int)col0 >> 7) & 15;
        const float qscale = 0.08838834764831845f;   // 1/sqrt(128)
#pragma unroll
        for (int s = 0; s < 4; s++)
#pragma unroll
            for (int t = 0; t < 4; t++) {
                const int d = wn + 8 * t + 2 * gx;   // 0..126 even
                const int p = d >> 1;
#pragma unroll
                for (int h = 0; h < 2; h++) {
                    long r = row0 + wm + 16 * s + gy + 8 * h;
                    int  b  = (int)(r >> 11);
                    int  tt = (int)r & 2047;
                    float v0 = acc[s][t][2 * h + 0];
                    float v1 = acc[s][t][2 * h + 1];
                    if (sec < 2) {
                        float c  = cosT[tt * 64 + p];
                        float sn = sinT[tt * 64 + p];
                        float e = v0, o = v1;
                        v0 = e * c - o * sn;
                        v1 = e * sn + o * c;
                        if (sec == 0) { v0 *= qscale; v1 *= qscale; }
                    }
                    v0 = f2tff(v0); v1 = f2tff(v1);
                    long bh = (long)b * NH + head;
                    if (sec == 2) {
                        g_Vt[(bh * HD + d)     * TT + tt] = v0;
                        g_Vt[(bh * HD + d + 1) * TT + tt] = v1;
                    } else {
                        float* dst = (sec == 0) ? g_Q : g_K;
                        *(float2*)&dst[(bh * TT + tt) * HD + d] = make_float2(v0, v1);
                    }
                }
            }
    } else {
#pragma unroll
        for (int t = 0; t < 4; t++) {
            const int n = (int)col0 + wn + 8 * t + 2 * gx;
            float2 bv = *(const float2*)&bias[n];
#pragma unroll
            for (int s = 0; s < 4; s++)
#pragma unroll
                for (int h = 0; h < 2; h++) {
                    long r = row0 + wm + 16 * s + gy + 8 * h;
                    *(float2*)&Cout[r * HID + n] =
                        make_float2(acc[s][t][2 * h] + bv.x, acc[s][t][2 * h + 1] + bv.y);
                }
        }
    }
}

// ---------------------------------------------------------------------------
// Flash attention via tf32 mma.
// One block per (bh, 128-row q tile). KV tiles of 32. 8 warps, each owns
// 16 q rows x full KV width -> warp-local softmax.
// smem: Qs[128][132], Ks[32][132], Vs[128][36] (V^T tile), Ps[128][36].
// ---------------------------------------------------------------------------
#define QT  128
#define KVT 32
#define LQK 132
#define LPV 36
#define ATTN_SMEM ((QT * LQK + KVT * LQK + HD * LPV + QT * LPV) * 4)  // 121344

__global__ __launch_bounds__(256, 1)
void attn_kernel()
{
    extern __shared__ float sm[];
    float* Qs = sm;                        // 128*132
    float* Ks = Qs + QT * LQK;             // 32*132
    float* Vs = Ks + KVT * LQK;            // 128*36
    float* Ps = Vs + HD * LPV;             // 128*36

    const int tid  = threadIdx.x;
    const int lane = tid & 31;
    const int w    = tid >> 5;
    const int gy   = lane >> 2;
    const int gx   = lane & 3;
    const int bh   = blockIdx.y;
    const int q0   = blockIdx.x * QT;
    const int qw   = w * 16;

    const float* __restrict__ Qg = g_Q  + (long)bh * TT * HD;
    const float* __restrict__ Kg = g_K  + (long)bh * TT * HD;
    const float* __restrict__ Vg = g_Vt + (long)bh * HD * TT;

    // Q tile: 128x128 floats = 4096 float4 / 256 thr = 16 each
#pragma unroll
    for (int i = 0; i < 16; i++) {
        int f = tid + i * 256;
        int r = f >> 5, c4 = f & 31;
        *(float4*)&Qs[r * LQK + c4 * 4] = *(const float4*)&Qg[(long)(q0 + r) * HD + c4 * 4];
    }

    float o[16][4];
#pragma unroll
    for (int dt = 0; dt < 16; dt++)
#pragma unroll
        for (int j = 0; j < 4; j++) o[dt][j] = 0.0f;
    float m0 = -3.0e38f, m1 = -3.0e38f, l0 = 0.0f, l1 = 0.0f;

    for (int kv0 = 0; kv0 < TT; kv0 += KVT) {
        __syncthreads();
        // K tile 32x128 = 1024 f4 / 256 = 4 each
#pragma unroll
        for (int i = 0; i < 4; i++) {
            int f = tid + i * 256;
            int r = f >> 5, c4 = f & 31;
            *(float4*)&Ks[r * LQK + c4 * 4] = *(const float4*)&Kg[(long)(kv0 + r) * HD + c4 * 4];
        }
        // V^T tile 128(d) x 32(kv) = 1024 f4 / 256 = 4 each
#pragma unroll
        for (int i = 0; i < 4; i++) {
            int f = tid + i * 256;
            int d = f >> 3, k4 = f & 7;
            *(float4*)&Vs[d * LPV + k4 * 4] = *(const float4*)&Vg[(long)d * TT + kv0 + k4 * 4];
        }
        __syncthreads();

        // S = Q . K^T : warp tile 16 x 32, k = 128
        float s4[4][4];
#pragma unroll
        for (int t = 0; t < 4; t++)
#pragma unroll
            for (int j = 0; j < 4; j++) s4[t][j] = 0.0f;

#pragma unroll
        for (int ks = 0; ks < 16; ks++) {
            const int k0 = ks * 8;
            uint32_t a[4];
            const float* qp = &Qs[(qw + gy) * LQK + k0 + gx];
            a[0] = __float_as_uint(qp[0]);
            a[1] = __float_as_uint(qp[8 * LQK]);
            a[2] = __float_as_uint(qp[4]);
            a[3] = __float_as_uint(qp[8 * LQK + 4]);
#pragma unroll
            for (int t = 0; t < 4; t++) {
                const float* kp = &Ks[(8 * t + gy) * LQK + k0 + gx];
                uint32_t b[2] = { __float_as_uint(kp[0]), __float_as_uint(kp[4]) };
                mma8(s4[t], a, b);
            }
        }

        // warp-local online softmax (rows qw+gy and qw+gy+8)
        float mx0 = -3.0e38f, mx1 = -3.0e38f;
#pragma unroll
        for (int t = 0; t < 4; t++) {
            mx0 = fmaxf(mx0, fmaxf(s4[t][0], s4[t][1]));
            mx1 = fmaxf(mx1, fmaxf(s4[t][2], s4[t][3]));
        }
        mx0 = fmaxf(mx0, __shfl_xor_sync(0xffffffffu, mx0, 1));
        mx0 = fmaxf(mx0, __shfl_xor_sync(0xffffffffu, mx0, 2));
        mx1 = fmaxf(mx1, __shfl_xor_sync(0xffffffffu, mx1, 1));
        mx1 = fmaxf(mx1, __shfl_xor_sync(0xffffffffu, mx1, 2));

        float mn0 = fmaxf(m0, mx0), mn1 = fmaxf(m1, mx1);
        float al0 = __expf(m0 - mn0), al1 = __expf(m1 - mn1);
        float sum0 = 0.0f, sum1 = 0.0f;
#pragma unroll
        for (int t = 0; t < 4; t++) {
            s4[t][0] = __expf(s4[t][0] - mn0);
            s4[t][1] = __expf(s4[t][1] - mn0);
            s4[t][2] = __expf(s4[t][2] - mn1);
            s4[t][3] = __expf(s4[t][3] - mn1);
            sum0 += s4[t][0] + s4[t][1];
            sum1 += s4[t][2] + s4[t][3];
        }
        sum0 += __shfl_xor_sync(0xffffffffu, sum0, 1);
        sum0 += __shfl_xor_sync(0xffffffffu, sum0, 2);
        sum1 += __shfl_xor_sync(0xffffffffu, sum1, 1);
        sum1 += __shfl_xor_sync(0xffffffffu, sum1, 2);

        l0 = l0 * al0 + sum0;  m0 = mn0;
        l1 = l1 * al1 + sum1;  m1 = mn1;

#pragma unroll
        for (int dt = 0; dt < 16; dt++) {
            o[dt][0] *= al0; o[dt][1] *= al0;
            o[dt][2] *= al1; o[dt][3] *= al1;
        }

        // P -> smem (tf32-rounded), per-warp region
#pragma unroll
        for (int t = 0; t < 4; t++) {
            *(float2*)&Ps[(qw + gy)     * LPV + 8 * t + 2 * gx] =
                make_float2(f2tff(s4[t][0]), f2tff(s4[t][1]));
            *(float2*)&Ps[(qw + gy + 8) * LPV + 8 * t + 2 * gx] =
                make_float2(f2tff(s4[t][2]), f2tff(s4[t][3]));
        }
        __syncwarp();

        // O += P . V : warp tile 16 x 128, k = 32
#pragma unroll
        for (int ks = 0; ks < 4; ks++) {
            const int k0 = ks * 8;
            uint32_t a[4];
            const float* pp = &Ps[(qw + gy) * LPV + k0 + gx];
            a[0] = __float_as_uint(pp[0]);
            a[1] = __float_as_uint(pp[8 * LPV]);
            a[2] = __float_as_uint(pp[4]);
            a[3] = __float_as_uint(pp[8 * LPV + 4]);
#pragma unroll
            for (int dt = 0; dt < 16; dt++) {
                const float* vp = &Vs[(8 * dt + gy) * LPV + k0 + gx];
                uint32_t b[2] = { __float_as_uint(vp[0]), __float_as_uint(vp[4]) };
                mma8(o[dt], a, b);
            }
        }
    }

    // finalize: /l, write [B,T,NH*HD]
    const int b = bh >> 4, h = bh & 15;
    const float inv0 = 1.0f / l0, inv1 = 1.0f / l1;
    const long t0 = q0 + qw + gy;
#pragma unroll
    for (int dt = 0; dt < 16; dt++) {
        int d = 8 * dt + 2 * gx;
        long base0 = ((long)b * TT + t0)     * HID + h * HD + d;
        long base1 = ((long)b * TT + t0 + 8) * HID + h * HD + d;
        *(float2*)&g_attn[base0] = make_float2(o[dt][0] * inv0, o[dt][1] * inv0);
        *(float2*)&g_attn[base1] = make_float2(o[dt][2] * inv1, o[dt][3] * inv1);
    }
}

// ---------------------------------------------------------------------------
extern "C" void kernel_launch(void* const* d_in, const int* in_sizes, int n_in,
                              void* d_out, int out_size)
{
    const float* x      = (const float*)d_in[0];
    const float* w_qkv  = (const float*)d_in[1];
    const float* w_proj = (const float*)d_in[2];
    const float* b_proj = (const float*)d_in[3];
    const float* cosT   = (const float*)d_in[4];
    const float* sinT   = (const float*)d_in[5];
    float* out = (float*)d_out;

    cudaFuncSetAttribute(attn_kernel,
                         cudaFuncAttributeMaxDynamicSharedMemorySize, ATTN_SMEM);

    // 1) QKV proj (tf32 mma) + RoPE + scatter (V transposed)
    gemm_kernel<0><<<dim3(MTOT / 128, (3 * HID) / 128), 256>>>(
        x, w_qkv, cosT, sinT, nullptr, nullptr);

    // 2) attention (tf32 mma)
    attn_kernel<<<dim3(TT / QT, BB * NH), 256, ATTN_SMEM>>>();

    // 3) out proj (tf32 mma) + bias
    gemm_kernel<1><<<dim3(MTOT / 128, HID / 128), 256>>>(
        nullptr, w_proj, nullptr, nullptr, b_proj, out);
}

// round 3
// speedup vs baseline: 4.5268x; 1.4322x over previous
#include <cuda_runtime.h>
#include <cstdint>

// Problem constants
#define BB   4
#define TT   2048
#define HID  2048
#define NH   16
#define HD   128
#define MTOT (BB * TT)          // 8192
#define KDIM 2048

// Scratch (device globals; allocation-free rule)
__device__ float g_x    [(size_t)MTOT * KDIM];        // tf32-rounded x
__device__ float g_wqkv [(size_t)3 * HID * KDIM];     // tf32-rounded w_qkv
__device__ float g_wproj[(size_t)HID * KDIM];         // tf32-rounded w_proj
__device__ float g_Q [(size_t)BB * NH * TT * HD];
__device__ float g_K [(size_t)BB * NH * TT * HD];
__device__ float g_Vt[(size_t)BB * NH * HD * TT];     // V^T: [bh][d][t]
__device__ float g_attn[(size_t)MTOT * HID];          // tf32-rounded attn out

// ---------------------------------------------------------------------------
// helpers
// ---------------------------------------------------------------------------
__device__ __forceinline__ float f2tff(float x) {
    uint32_t r;
    asm("cvt.rna.tf32.f32 %0, %1;" : "=r"(r) : "f"(x));
    return __uint_as_float(r);
}
__device__ __forceinline__ void mma8(float* c, const uint32_t* a, const uint32_t* b) {
    asm volatile(
        "mma.sync.aligned.m16n8k8.row.col.f32.tf32.tf32.f32 "
        "{%0,%1,%2,%3},{%4,%5,%6,%7},{%8,%9},{%0,%1,%2,%3};\n"
        : "+f"(c[0]), "+f"(c[1]), "+f"(c[2]), "+f"(c[3])
        : "r"(a[0]), "r"(a[1]), "r"(a[2]), "r"(a[3]), "r"(b[0]), "r"(b[1]));
}
__device__ __forceinline__ uint32_t smem_u32(const void* p) {
    return (uint32_t)__cvta_generic_to_shared(p);
}
#define CP16(dst_u32, src_ptr) \
    asm volatile("cp.async.cg.shared.global [%0], [%1], 16;\n" :: "r"(dst_u32), "l"(src_ptr))
#define CP_COMMIT() asm volatile("cp.async.commit_group;\n" ::)
#define CP_WAIT1()  asm volatile("cp.async.wait_group 1;\n" ::)

// ---------------------------------------------------------------------------
// pre-round inputs to tf32
// ---------------------------------------------------------------------------
template <int WHICH>
__global__ void round_kernel(const float* __restrict__ src, int n)
{
    float* dst = (WHICH == 0) ? g_x : (WHICH == 1) ? g_wqkv : g_wproj;
    int stride = gridDim.x * blockDim.x * 4;
    for (int i = (blockIdx.x * blockDim.x + threadIdx.x) * 4; i < n; i += stride) {
        float4 v = *(const float4*)(src + i);
        *(float4*)(dst + i) = make_float4(f2tff(v.x), f2tff(v.y), f2tff(v.z), f2tff(v.w));
    }
}

// ---------------------------------------------------------------------------
// GEMM: C[M,N] = A[M,K] * Bw[N,K]^T  via m16n8k8 tf32 mma.
// Tiles 128x128x32, 256 thr = 8 warps (2m x 4n), warp tile 64x32.
// cp.async 3-stage pipeline; smem rows of 32 floats with XOR-swizzled f4 cols.
// MODE 0: A=g_x, Bw=g_wqkv; epilogue RoPE+qscale, scatter Q/K (V transposed).
// MODE 1: A=g_attn, Bw=g_wproj; epilogue + bias -> Cout.
// ---------------------------------------------------------------------------
#define GSTAGES 3
#define GEMM_SMEM (GSTAGES * 2 * 128 * 32 * 4)   // 98304 bytes

template <int MODE>
__global__ __launch_bounds__(256, 2)
void gemm_kernel(const float* __restrict__ cosT,
                 const float* __restrict__ sinT,
                 const float* __restrict__ bias,
                 float* __restrict__ Cout)
{
    extern __shared__ float sm[];
    float* As = sm;                        // GSTAGES * 4096
    float* Bs = sm + GSTAGES * 4096;

    const int tid  = threadIdx.x;
    const int lane = tid & 31;
    const int w    = tid >> 5;
    const int gy   = lane >> 2;   // 0..7
    const int gx   = lane & 3;    // 0..3
    const int wm   = (w >> 2) * 64;
    const int wn   = (w & 3) * 32;
    const long row0 = (long)blockIdx.x * 128;
    const long col0 = (long)blockIdx.y * 128;

    const float* __restrict__ Ap = (MODE == 0) ? g_x    : g_attn;
    const float* __restrict__ Bp = (MODE == 0) ? g_wqkv : g_wproj;

    // per-thread load map: 4 float4 per operand per stage
    int lr[4], lc4[4], soff[4];
#pragma unroll
    for (int j = 0; j < 4; j++) {
        int f = tid + j * 256;
        lr[j]  = f >> 3;            // 0..127
        lc4[j] = f & 7;             // f4 col 0..7
        soff[j] = (lr[j] * 32 + ((lc4[j] ^ (lr[j] & 7)) * 4)) * 4;   // bytes
    }
    const uint32_t sA = smem_u32(As);
    const uint32_t sB = smem_u32(Bs);

    auto issue = [&](int kb, int slot) {
        if (kb < KDIM) {
            const uint32_t ba = sA + slot * 16384;
            const uint32_t bb = sB + slot * 16384;
#pragma unroll
            for (int j = 0; j < 4; j++) {
                CP16(ba + soff[j], Ap + (row0 + lr[j]) * KDIM + kb + lc4[j] * 4);
                CP16(bb + soff[j], Bp + (col0 + lr[j]) * KDIM + kb + lc4[j] * 4);
            }
        }
        CP_COMMIT();
    };

    float acc[4][4][4];
#pragma unroll
    for (int s = 0; s < 4; s++)
#pragma unroll
        for (int t = 0; t < 4; t++)
#pragma unroll
            for (int j = 0; j < 4; j++) acc[s][t][j] = 0.0f;

    issue(0, 0);
    issue(32, 1);

    for (int it = 0; it < KDIM / 32; it++) {
        issue((it + 2) * 32, (it + 2) % GSTAGES);
        CP_WAIT1();
        __syncthreads();

        const float* Sa = As + (it % GSTAGES) * 4096;
        const float* Sb = Bs + (it % GSTAGES) * 4096;
#pragma unroll
        for (int ks = 0; ks < 4; ks++) {
            const int i0 = ((2 * ks)     ^ gy) * 4 + gx;
            const int i1 = ((2 * ks + 1) ^ gy) * 4 + gx;
            uint32_t af[4][4], bf[4][2];
#pragma unroll
            for (int s = 0; s < 4; s++) {
                const float* p = Sa + (wm + 16 * s + gy) * 32;
                af[s][0] = __float_as_uint(p[i0]);
                af[s][1] = __float_as_uint(p[i0 + 256]);
                af[s][2] = __float_as_uint(p[i1]);
                af[s][3] = __float_as_uint(p[i1 + 256]);
            }
#pragma unroll
            for (int t = 0; t < 4; t++) {
                const float* p = Sb + (wn + 8 * t + gy) * 32;
                bf[t][0] = __float_as_uint(p[i0]);
                bf[t][1] = __float_as_uint(p[i1]);
            }
#pragma unroll
            for (int s = 0; s < 4; s++)
#pragma unroll
                for (int t = 0; t < 4; t++)
                    mma8(acc[s][t], af[s], bf[t]);
        }
        __syncthreads();
    }

    // Epilogue. C mapping: rows wm+16s+gy(+8), cols wn+8t+2gx(+1).
    if (MODE == 0) {
        const int sec  = (int)(col0 >> 11);          // 0=Q 1=K 2=V
        const int head = ((int)col0 >> 7) & 15;
        const float qscale = 0.08838834764831845f;   // 1/sqrt(128)
#pragma unroll
        for (int s = 0; s < 4; s++)
#pragma unroll
            for (int t = 0; t < 4; t++) {
                const int d = wn + 8 * t + 2 * gx;
                const int p = d >> 1;
#pragma unroll
                for (int h = 0; h < 2; h++) {
                    long r = row0 + wm + 16 * s + gy + 8 * h;
                    int  b  = (int)(r >> 11);
                    int  tt = (int)r & 2047;
                    float v0 = acc[s][t][2 * h + 0];
                    float v1 = acc[s][t][2 * h + 1];
                    if (sec < 2) {
                        float c  = cosT[tt * 64 + p];
                        float sn = sinT[tt * 64 + p];
                        float e = v0, o = v1;
                        v0 = e * c - o * sn;
                        v1 = e * sn + o * c;
                        if (sec == 0) { v0 *= qscale; v1 *= qscale; }
                    }
                    v0 = f2tff(v0); v1 = f2tff(v1);
                    long bh = (long)b * NH + head;
                    if (sec == 2) {
                        g_Vt[(bh * HD + d)     * TT + tt] = v0;
                        g_Vt[(bh * HD + d + 1) * TT + tt] = v1;
                    } else {
                        float* dst = (sec == 0) ? g_Q : g_K;
                        *(float2*)&dst[(bh * TT + tt) * HD + d] = make_float2(v0, v1);
                    }
                }
            }
    } else {
#pragma unroll
        for (int t = 0; t < 4; t++) {
            const int n = (int)col0 + wn + 8 * t + 2 * gx;
            float2 bv = *(const float2*)&bias[n];
#pragma unroll
            for (int s = 0; s < 4; s++)
#pragma unroll
                for (int h = 0; h < 2; h++) {
                    long r = row0 + wm + 16 * s + gy + 8 * h;
                    *(float2*)&Cout[r * HID + n] =
                        make_float2(acc[s][t][2 * h] + bv.x, acc[s][t][2 * h + 1] + bv.y);
                }
        }
    }
}

// ---------------------------------------------------------------------------
// Flash attention via tf32 mma + cp.async double-buffered K/V tiles.
// One block per (bh, 128-row q tile). KV tiles of 32. 8 warps, each 16 q rows.
// Q: [128][128] XOR-swizzled. K stages: [2][32][128] swizzled.
// Vt stages: [2][128][32] swizzled. Ps: [128][36] padded.
// ---------------------------------------------------------------------------
#define QT  128
#define KVT 32
#define LPV 36
// floats: Q 16384 + K 2*4096 + V 2*4096 + P 4608 = 37376
#define ATTN_SMEM (37376 * 4)

__global__ __launch_bounds__(256, 1)
void attn_kernel()
{
    extern __shared__ float sm[];
    float* Qs  = sm;                  // 128*128
    float* Kst = Qs + 16384;          // 2 * 32*128
    float* Vst = Kst + 8192;          // 2 * 128*32
    float* Ps  = Vst + 8192;          // 128*36

    const int tid  = threadIdx.x;
    const int lane = tid & 31;
    const int w    = tid >> 5;
    const int gy   = lane >> 2;
    const int gx   = lane & 3;
    const int bh   = blockIdx.y;
    const int q0   = blockIdx.x * QT;
    const int qw   = w * 16;

    const float* __restrict__ Qg = g_Q  + (long)bh * TT * HD;
    const float* __restrict__ Kg = g_K  + (long)bh * TT * HD;
    const float* __restrict__ Vg = g_Vt + (long)bh * HD * TT;

    const uint32_t sK = smem_u32(Kst);
    const uint32_t sV = smem_u32(Vst);

    // Q tile load, swizzled (rows of 32 f4 cols: col' = (c4&24)|((c4&7)^(r&7)))
#pragma unroll
    for (int i = 0; i < 16; i++) {
        int f = tid + i * 256;
        int r = f >> 5, c4 = f & 31;
        int cs = (c4 & 24) | ((c4 & 7) ^ (r & 7));
        *(float4*)&Qs[r * 128 + cs * 4] = *(const float4*)&Qg[(long)(q0 + r) * HD + c4 * 4];
    }

    auto issueKV = [&](int kv0, int slot) {
        if (kv0 < TT) {
#pragma unroll
            for (int i = 0; i < 4; i++) {
                int f = tid + i * 256;
                int r = f >> 5, c4 = f & 31;
                int cs = (c4 & 24) | ((c4 & 7) ^ (r & 7));
                CP16(sK + (slot * 4096 + r * 128 + cs * 4) * 4,
                     Kg + (long)(kv0 + r) * HD + c4 * 4);
            }
#pragma unroll
            for (int i = 0; i < 4; i++) {
                int f = tid + i * 256;
                int d = f >> 3, k4 = f & 7;
                CP16(sV + (slot * 4096 + d * 32 + ((k4 ^ (d & 7)) * 4)) * 4,
                     Vg + (long)d * TT + kv0 + k4 * 4);
            }
        }
        CP_COMMIT();
    };

    float o[16][4];
#pragma unroll
    for (int dt = 0; dt < 16; dt++)
#pragma unroll
        for (int j = 0; j < 4; j++) o[dt][j] = 0.0f;
    float m0 = -3.0e38f, m1 = -3.0e38f, l0 = 0.0f, l1 = 0.0f;

    issueKV(0, 0);

    for (int i = 0; i < TT / KVT; i++) {
        issueKV((i + 1) * KVT, (i + 1) & 1);
        CP_WAIT1();
        __syncthreads();

        const float* Ks = Kst + (i & 1) * 4096;
        const float* Vs = Vst + (i & 1) * 4096;

        // S = Q . K^T : warp tile 16 x 32, k = 128
        float s4[4][4];
#pragma unroll
        for (int t = 0; t < 4; t++)
#pragma unroll
            for (int j = 0; j < 4; j++) s4[t][j] = 0.0f;

#pragma unroll
        for (int ks = 0; ks < 16; ks++) {
            const int c0 = 2 * ks, c1 = 2 * ks + 1;
            const int i0 = ((c0 & 24) | ((c0 & 7) ^ gy)) * 4 + gx;
            const int i1 = ((c1 & 24) | ((c1 & 7) ^ gy)) * 4 + gx;
            uint32_t a[4];
            const float* qp = Qs + (qw + gy) * 128;
            a[0] = __float_as_uint(qp[i0]);
            a[1] = __float_as_uint(qp[i0 + 1024]);
            a[2] = __float_as_uint(qp[i1]);
            a[3] = __float_as_uint(qp[i1 + 1024]);
#pragma unroll
            for (int t = 0; t < 4; t++) {
                const float* kp = Ks + (8 * t + gy) * 128;
                uint32_t b[2] = { __float_as_uint(kp[i0]), __float_as_uint(kp[i1]) };
                mma8(s4[t], a, b);
            }
        }

        // warp-local online softmax (rows qw+gy and qw+gy+8)
        float mx0 = -3.0e38f, mx1 = -3.0e38f;
#pragma unroll
        for (int t = 0; t < 4; t++) {
            mx0 = fmaxf(mx0, fmaxf(s4[t][0], s4[t][1]));
            mx1 = fmaxf(mx1, fmaxf(s4[t][2], s4[t][3]));
        }
        mx0 = fmaxf(mx0, __shfl_xor_sync(0xffffffffu, mx0, 1));
        mx0 = fmaxf(mx0, __shfl_xor_sync(0xffffffffu, mx0, 2));
        mx1 = fmaxf(mx1, __shfl_xor_sync(0xffffffffu, mx1, 1));
        mx1 = fmaxf(mx1, __shfl_xor_sync(0xffffffffu, mx1, 2));

        float mn0 = fmaxf(m0, mx0), mn1 = fmaxf(m1, mx1);
        float al0 = __expf(m0 - mn0), al1 = __expf(m1 - mn1);
        float sum0 = 0.0f, sum1 = 0.0f;
#pragma unroll
        for (int t = 0; t < 4; t++) {
            s4[t][0] = __expf(s4[t][0] - mn0);
            s4[t][1] = __expf(s4[t][1] - mn0);
            s4[t][2] = __expf(s4[t][2] - mn1);
            s4[t][3] = __expf(s4[t][3] - mn1);
            sum0 += s4[t][0] + s4[t][1];
            sum1 += s4[t][2] + s4[t][3];
        }
        sum0 += __shfl_xor_sync(0xffffffffu, sum0, 1);
        sum0 += __shfl_xor_sync(0xffffffffu, sum0, 2);
        sum1 += __shfl_xor_sync(0xffffffffu, sum1, 1);
        sum1 += __shfl_xor_sync(0xffffffffu, sum1, 2);

        l0 = l0 * al0 + sum0;  m0 = mn0;
        l1 = l1 * al1 + sum1;  m1 = mn1;

#pragma unroll
        for (int dt = 0; dt < 16; dt++) {
            o[dt][0] *= al0; o[dt][1] *= al0;
            o[dt][2] *= al1; o[dt][3] *= al1;
        }

        // P -> smem (tf32-rounded), per-warp region
#pragma unroll
        for (int t = 0; t < 4; t++) {
            *(float2*)&Ps[(qw + gy)     * LPV + 8 * t + 2 * gx] =
                make_float2(f2tff(s4[t][0]), f2tff(s4[t][1]));
            *(float2*)&Ps[(qw + gy + 8) * LPV + 8 * t + 2 * gx] =
                make_float2(f2tff(s4[t][2]), f2tff(s4[t][3]));
        }
        __syncwarp();

        // O += P . V : warp tile 16 x 128, k = 32
#pragma unroll
        for (int ks = 0; ks < 4; ks++) {
            const int k0 = ks * 8;
            const int i0 = ((2 * ks)     ^ gy) * 4 + gx;
            const int i1 = ((2 * ks + 1) ^ gy) * 4 + gx;
            uint32_t a[4];
            const float* pp = Ps + (qw + gy) * LPV + k0;
            a[0] = __float_as_uint(pp[gx]);
            a[1] = __float_as_uint(pp[8 * LPV + gx]);
            a[2] = __float_as_uint(pp[gx + 4]);
            a[3] = __float_as_uint(pp[8 * LPV + gx + 4]);
#pragma unroll
            for (int dt = 0; dt < 16; dt++) {
                const float* vp = Vs + (8 * dt + gy) * 32;
                uint32_t b[2] = { __float_as_uint(vp[i0]), __float_as_uint(vp[i1]) };
                mma8(o[dt], a, b);
            }
        }
        __syncthreads();
    }

    // finalize: /l, tf32-round (input of out-proj), write [B,T,NH*HD]
    const int b = bh >> 4, h = bh & 15;
    const float inv0 = 1.0f / l0, inv1 = 1.0f / l1;
    const long t0 = q0 + qw + gy;
#pragma unroll
    for (int dt = 0; dt < 16; dt++) {
        int d = 8 * dt + 2 * gx;
        long base0 = ((long)b * TT + t0)     * HID + h * HD + d;
        long base1 = ((long)b * TT + t0 + 8) * HID + h * HD + d;
        *(float2*)&g_attn[base0] = make_float2(f2tff(o[dt][0] * inv0), f2tff(o[dt][1] * inv0));
        *(float2*)&g_attn[base1] = make_float2(f2tff(o[dt][2] * inv1), f2tff(o[dt][3] * inv1));
    }
}

// ---------------------------------------------------------------------------
extern "C" void kernel_launch(void* const* d_in, const int* in_sizes, int n_in,
                              void* d_out, int out_size)
{
    const float* x      = (const float*)d_in[0];
    const float* w_qkv  = (const float*)d_in[1];
    const float* w_proj = (const float*)d_in[2];
    const float* b_proj = (const float*)d_in[3];
    const float* cosT   = (const float*)d_in[4];
    const float* sinT   = (const float*)d_in[5];
    float* out = (float*)d_out;

    cudaFuncSetAttribute(gemm_kernel<0>,
                         cudaFuncAttributeMaxDynamicSharedMemorySize, GEMM_SMEM);
    cudaFuncSetAttribute(gemm_kernel<1>,
                         cudaFuncAttributeMaxDynamicSharedMemorySize, GEMM_SMEM);
    cudaFuncSetAttribute(attn_kernel,
                         cudaFuncAttributeMaxDynamicSharedMemorySize, ATTN_SMEM);

    // 0) pre-round inputs to tf32
    round_kernel<0><<<1024, 256>>>(x,      MTOT * KDIM);
    round_kernel<1><<<1024, 256>>>(w_qkv,  3 * HID * KDIM);
    round_kernel<2><<<1024, 256>>>(w_proj, HID * KDIM);

    // 1) QKV proj + RoPE + scatter (V transposed)
    gemm_kernel<0><<<dim3(MTOT / 128, (3 * HID) / 128), 256, GEMM_SMEM>>>(
        cosT, sinT, nullptr, nullptr);

    // 2) attention
    attn_kernel<<<dim3(TT / QT, BB * NH), 256, ATTN_SMEM>>>();

    // 3) out proj + bias
    gemm_kernel<1><<<dim3(MTOT / 128, HID / 128), 256, GEMM_SMEM>>>(
        nullptr, nullptr, b_proj, out);
}